// round 3
// baseline (speedup 1.0000x reference)
#include <cuda_runtime.h>

// CTC forward loss, T=512, N=32, C=8000, S=40 (Se = 2S+1 = 81).
// One WARP per batch element; 3 consecutive CTC states per lane (lanes 0-26
// real, 27-31 clamped duplicates). Alpha lives in registers; the s-1/s-2
// neighbor terms come from two shfl.up per step — no shared memory, no
// __syncthreads in the recurrence. Log2 domain (LOG_TINY == -126 exactly).
// 3-operand LSE uses the sorted form so the max contributes the constant 1:
// 3 MUFU per state instead of 4.

#define TT 512
#define NB 32
#define CC 8000
#define SS 40
#define SE 81        // 2*SS + 1
#define PF 8         // prefetch depth (ring of lp gathers)

#define NEGF     (-1.0e30f)
#define INV_LN2  1.44269504088896341f
#define LN2      0.69314718055994531f

__device__ __forceinline__ float ex2f_(float x) {
    float y; asm("ex2.approx.ftz.f32 %0, %1;" : "=f"(y) : "f"(x)); return y;
}
__device__ __forceinline__ float lg2f_(float x) {
    float y; asm("lg2.approx.ftz.f32 %0, %1;" : "=f"(y) : "f"(x)); return y;
}

// log2-sum-exp of {x, y, z}; exp of the max is exactly 1 (2 ex2 + 1 lg2).
__device__ __forceinline__ float lse3(float x, float y, float z) {
    const float hi = fmaxf(x, y), lo = fminf(x, y);
    const float m  = fmaxf(hi, z), z2 = fminf(hi, z);
    return m + lg2f_(1.0f + ex2f_(lo - m) + ex2f_(z2 - m));
}

__global__ __launch_bounds__(32, 1)
void ctc_warp_kernel(const float* __restrict__ lp,      // (T, N, C)
                     const int*   __restrict__ targets, // (N, S)
                     const int*   __restrict__ tgt_len, // (N,)
                     float*       __restrict__ out)     // (N,)
{
    const int n    = blockIdx.x;
    const int lane = threadIdx.x;
    // Lane owns states sb, sb+1, sb+2. Lanes 27-31 clamp to 78 (benign dups).
    const int sb = (3 * lane <= SE - 3) ? 3 * lane : (SE - 3);

    int  cls[3];
    bool skip[3];
#pragma unroll
    for (int k = 0; k < 3; ++k) {
        const int s = sb + k;
        if (s & 1) {
            cls[k]  = targets[n * SS + (s >> 1)];
            skip[k] = (s >= 3) && (cls[k] != targets[n * SS + ((s - 3) >> 1)]);
        } else {
            cls[k]  = 0;           // blank
            skip[k] = false;
        }
    }

    unsigned base[3];
#pragma unroll
    for (int k = 0; k < 3; ++k) base[k] = (unsigned)n * CC + (unsigned)cls[k];
    const unsigned stride = (unsigned)NB * CC;   // floats per timestep

    // t = 0 init (log2 domain); log2(float32 tiny) == -126 exactly.
    float a0, a1, a2;
    {
        const float l0 = __ldg(lp + base[0]) * INV_LN2;
        const float l1 = __ldg(lp + base[1]) * INV_LN2;
        a0 = (sb == 0) ? l0 : -126.0f;
        a1 = (sb == 0) ? l1 : -126.0f;
        a2 = -126.0f;
    }

    // Preload lp for t = 1..PF. ring[k][j] holds timestep tb+j of class k.
    float ring[3][PF];
#pragma unroll
    for (int j = 0; j < PF; ++j) {
        const unsigned off = (unsigned)(j + 1) * stride;
#pragma unroll
        for (int k = 0; k < 3; ++k) ring[k][j] = __ldg(lp + base[k] + off);
    }

    for (int tb = 1; tb < TT; tb += PF) {
#pragma unroll
        for (int jj = 0; jj < PF; ++jj) {
            const int t = tb + jj;
            if (t >= TT) break;   // only trims the final block

            const float l0 = ring[0][jj] * INV_LN2;
            const float l1 = ring[1][jj] * INV_LN2;
            const float l2 = ring[2][jj] * INV_LN2;
            if (t + PF < TT) {
                const unsigned off = (unsigned)(t + PF) * stride;
                ring[0][jj] = __ldg(lp + base[0] + off);
                ring[1][jj] = __ldg(lp + base[1] + off);
                ring[2][jj] = __ldg(lp + base[2] + off);
            }

            // Neighbor alphas from the previous lane (its slots 1 and 2).
            float p1 = __shfl_up_sync(0xffffffffu, a1, 1);
            float p2 = __shfl_up_sync(0xffffffffu, a2, 1);
            if (lane == 0) { p1 = NEGF; p2 = NEGF; }

            const float n0 = lse3(a0, p2, skip[0] ? p1 : NEGF) + l0;
            const float n1 = lse3(a1, a0, skip[1] ? p2 : NEGF) + l1;
            const float n2 = lse3(a2, a1, skip[2] ? a0 : NEGF) + l2;
            a0 = n0; a1 = n1; a2 = n2;
        }
    }

    // Publish final alphas (real lanes only) and reduce on lane 0.
    __shared__ float fin[SE];
    if (3 * lane == sb) { fin[sb] = a0; fin[sb + 1] = a1; fin[sb + 2] = a2; }
    __syncwarp();
    if (lane == 0) {
        const int   L    = tgt_len[n];
        const int   len  = 2 * L + 1;
        const float al   = fin[len - 1];
        const float ap   = fin[len - 2];
        const float x    = fmaxf(al, ap);
        const float y    = fminf(al, ap);
        const float loss = (x + lg2f_(1.0f + ex2f_(y - x))) * LN2;  // ln domain
        out[n] = -loss / (float)L;
    }
}

extern "C" void kernel_launch(void* const* d_in, const int* in_sizes, int n_in,
                              void* d_out, int out_size) {
    const float* lp      = (const float*)d_in[0];  // log_probs (T, N, C)
    const int*   targets = (const int*)  d_in[1];  // (N, S)
    // d_in[2] = input_lengths — reference ignores them (always full T)
    const int*   tlen    = (const int*)  d_in[3];  // (N,)
    ctc_warp_kernel<<<NB, 32>>>(lp, targets, tlen, (float*)d_out);
}

// round 6
// speedup vs baseline: 4.4227x; 4.4227x over previous
#include <cuda_runtime.h>

// CTC forward loss, T=512, N=32, C=8000, S=40 (Se = 2S+1 = 81).
//
// One block (128 threads, 4 warps) per batch element; ONE state per thread.
// Warp w covers states [18w, 18w+31] (14-state overlap between neighbors).
// In-warp neighbor alphas (s-1, s-2) come from shfl.up — no barrier.
// A warp's low-edge lanes lack cross-warp data; the resulting corruption
// propagates upward only 2 lanes per step, so for K=7 steps the wrong set
// stays inside lanes 0..13 (the overlap). Every 7 steps one __syncthreads
// refreshes lanes 0..13 of warp w from warp w-1's lanes 18..31, which are
// exact at all times (warp 0 is exact everywhere: its low edge is the true
// -inf boundary). All stale values remain finite, so nothing poisonous can
// reach owned lanes. Barrier cost is amortized 7x vs the naive layout.
//
// Log2 domain throughout (LOG_TINY = ln(2^-126) -> exactly -126.0).
// Sorted 3-way LSE: max contributes the constant 1 -> 2 ex2 + 1 lg2.

#define TT 512
#define NB 32
#define CC 8000
#define SS 40
#define SE 81        // 2*SS + 1
#define STRD 18      // warp-to-warp state offset (overlap = 32 - 18 = 14)
#define KSTEP 7      // barrier-free steps per refresh (needs 2*K <= 14)
#define PF 7         // prefetch ring depth == KSTEP (keeps indices static)

#define NEGF     (-1.0e30f)
#define INV_LN2  1.44269504088896341f
#define LN2      0.69314718055994531f

__device__ __forceinline__ float ex2f_(float x) {
    float y; asm("ex2.approx.ftz.f32 %0, %1;" : "=f"(y) : "f"(x)); return y;
}
__device__ __forceinline__ float lg2f_(float x) {
    float y; asm("lg2.approx.ftz.f32 %0, %1;" : "=f"(y) : "f"(x)); return y;
}

__global__ __launch_bounds__(128, 1)
void ctc_ovl_kernel(const float* __restrict__ lp,      // (T, N, C)
                    const int*   __restrict__ targets, // (N, S)
                    const int*   __restrict__ tgt_len, // (N,)
                    float*       __restrict__ out)     // (N,)
{
    const int n   = blockIdx.x;
    const int tid = threadIdx.x;
    const int w   = tid >> 5;
    const int L   = tid & 31;

    const int s_nom = STRD * w + L;                 // nominal state (may exceed 80)
    const int s     = (s_nom <= SE - 1) ? s_nom : (SE - 1);

    // Expanded label: even state -> blank(0); odd -> targets[(s-1)/2].
    int  cls  = 0;
    bool skip = false;
    if (s & 1) {
        cls  = targets[n * SS + (s >> 1)];
        skip = (s >= 3) && (cls != targets[n * SS + ((s - 3) >> 1)]);
    }
    // Note: if skip is true then s>=3, so lane has valid shfl.up(2) wherever
    // the value matters (warp 0: L == s >= 3; other warps: owned lanes >= 14).

    const unsigned base   = (unsigned)n * CC + (unsigned)cls;
    const unsigned stride = (unsigned)NB * CC;

    __shared__ float xfer[2][4][14];   // refresh buffers (parity double-buffered)
    __shared__ float fin[SE];          // final alphas

    // t = 0 init (log2 domain).
    float a;
    {
        const float l0 = __ldg(lp + base) * INV_LN2;
        a = (s_nom <= 1) ? l0 : -126.0f;
    }

    // Preload lp for t = 1..PF (own class only).
    float ring[PF];
#pragma unroll
    for (int j = 0; j < PF; ++j)
        ring[j] = __ldg(lp + base + (unsigned)(j + 1) * stride);

    const bool lane0 = (L == 0);

    int par = 0;
    for (int tb = 1; tb < TT; tb += KSTEP) {       // 73 super-steps: t = 1..511
#pragma unroll
        for (int j = 0; j < KSTEP; ++j) {
            const int t = tb + j;
            const float l = ring[j] * INV_LN2;
            if (t + PF < TT)
                ring[j] = __ldg(lp + base + (unsigned)(t + PF) * stride);

            float p1 = __shfl_up_sync(0xffffffffu, a, 1);
            float p2 = __shfl_up_sync(0xffffffffu, a, 2);
            p1 = lane0 ? NEGF : p1;                // true boundary for warp 0
            const float p2v = skip ? p2 : NEGF;    // skip transition gate

            // sorted LSE3: exp of the max is exactly 1
            const float hi = fmaxf(a, p1), lo = fminf(a, p1);
            const float m  = fmaxf(hi, p2v), z = fminf(hi, p2v);
            a = m + lg2f_(1.0f + ex2f_(lo - m) + ex2f_(z - m)) + l;
        }

        // Refresh: warp w-1 lanes 18..31 -> warp w lanes 0..13.
        if (L >= STRD) xfer[par][w][L - STRD] = a;
        __syncthreads();
        if (w > 0 && L < 14) a = xfer[par][w - 1][L];
        par ^= 1;
    }

    // Owned (always-exact) lanes publish final alphas.
    const bool owner = (w == 0) || (L >= 14 && s_nom <= SE - 1);
    if (owner) fin[s_nom] = a;
    __syncthreads();

    if (tid == 0) {
        const int   Ln   = tgt_len[n];
        const int   len  = 2 * Ln + 1;
        const float al   = fin[len - 1];
        const float ap   = fin[len - 2];
        const float x    = fmaxf(al, ap);
        const float y    = fminf(al, ap);
        const float loss = (x + lg2f_(1.0f + ex2f_(y - x))) * LN2;  // back to ln
        out[n] = -loss / (float)Ln;
    }
}

extern "C" void kernel_launch(void* const* d_in, const int* in_sizes, int n_in,
                              void* d_out, int out_size) {
    const float* lp      = (const float*)d_in[0];  // log_probs (T, N, C)
    const int*   targets = (const int*)  d_in[1];  // (N, S)
    // d_in[2] = input_lengths — reference ignores them (always full T)
    const int*   tlen    = (const int*)  d_in[3];  // (N,)
    ctc_ovl_kernel<<<NB, 128>>>(lp, targets, tlen, (float*)d_out);
}